// round 10
// baseline (speedup 1.0000x reference)
#include <cuda_runtime.h>
#include <cuda_fp16.h>

#define DK 32
#define ODIM 32
#define MAX_NODES 100002
#define MAX_N 100000
#define NPW 2            // nodes per warp
#define WPB 4            // warps per block (block = 128 threads)

// Scratch (device globals — no allocation in kernel_launch)
__device__ int g_row_ptr[MAX_NODES];
// Packed per-node 128B line of 16B chunks; chunk qd = [K quad qd | V quad qd] halves.
__device__ __align__(16) __half g_KV[MAX_N * 2 * DK];

// ---------------------------------------------------------------------------
// Prep kernel (fused): blocks [0, packBlocks) pack interleaved fp16 KV;
// remaining blocks build CSR row pointers (4 edges/thread via int4).
// ---------------------------------------------------------------------------
__global__ __launch_bounds__(256) void prep_kernel(
    const float* __restrict__ Kf,
    const float* __restrict__ Vf,
    const int*   __restrict__ dst,
    int N, int E, int packBlocks)
{
    if ((int)blockIdx.x < packBlocks) {
        const int c = blockIdx.x * 256 + threadIdx.x;
        if (c >= N * 8) return;
        const int node = c >> 3;
        const int qd   = c & 7;
        const float4 kq = *reinterpret_cast<const float4*>(Kf + (size_t)node * DK + qd * 4);
        const float4 vq = *reinterpret_cast<const float4*>(Vf + (size_t)node * DK + qd * 4);
        __half2 h0 = __floats2half2_rn(kq.x, kq.y);
        __half2 h1 = __floats2half2_rn(kq.z, kq.w);
        __half2 h2 = __floats2half2_rn(vq.x, vq.y);
        __half2 h3 = __floats2half2_rn(vq.z, vq.w);
        uint4 o;
        o.x = *reinterpret_cast<unsigned*>(&h0);
        o.y = *reinterpret_cast<unsigned*>(&h1);
        o.z = *reinterpret_cast<unsigned*>(&h2);
        o.w = *reinterpret_cast<unsigned*>(&h3);
        reinterpret_cast<uint4*>(g_KV)[c] = o;
    } else {
        const int t  = (blockIdx.x - packBlocks) * 256 + threadIdx.x;
        const int e0 = t * 4;
        if (e0 >= E) return;
        int ds[4];
        if (e0 + 3 < E) {
            const int4 d4 = *reinterpret_cast<const int4*>(dst + e0);
            ds[0] = d4.x; ds[1] = d4.y; ds[2] = d4.z; ds[3] = d4.w;
        } else {
            #pragma unroll
            for (int j = 0; j < 4; ++j) ds[j] = (e0 + j < E) ? dst[e0 + j] : 0;
        }
        int p = (e0 > 0) ? dst[e0 - 1] : -1;
        #pragma unroll
        for (int j = 0; j < 4; ++j) {
            const int e = e0 + j;
            if (e < E) {
                const int d = ds[j];
                for (int n = p + 1; n <= d; ++n) g_row_ptr[n] = e;
                p = d;
                if (e == E - 1)
                    for (int n = d + 1; n <= N; ++n) g_row_ptr[n] = E;
            }
        }
    }
}

// ---------------------------------------------------------------------------
// Fused gat kernel: one warp per NPW nodes; 8-lane groups fetch ONE packed KV
// line per edge (one LDG.128 per lane covers its K-quad AND V-quad).
// ---------------------------------------------------------------------------
__global__ __launch_bounds__(128, 12) void gat_kernel(
    const float* __restrict__ X,
    const float* __restrict__ Wo,
    const float* __restrict__ bo,
    const int*   __restrict__ src,
    float* __restrict__ out,
    int N)
{
    const unsigned FULL = 0xffffffffu;
    __shared__ float4 sWoT4[ODIM][9];   // sWoT4[c][dq] = Wo[4dq..4dq+3][c], padded
    __shared__ float sBo[ODIM];
    __shared__ __align__(16) float sAgg[WPB][DK];

    for (int i = threadIdx.x; i < DK * ODIM; i += blockDim.x) {
        const int d = i >> 5, c = i & 31;
        reinterpret_cast<float*>(&sWoT4[c][0])[d] = Wo[i];
    }
    if (threadIdx.x < ODIM) sBo[threadIdx.x] = bo[threadIdx.x];
    __syncthreads();

    const int lane = threadIdx.x & 31;
    const int wib  = threadIdx.x >> 5;
    const int warp = (blockIdx.x * blockDim.x + threadIdx.x) >> 5;
    const int node0 = warp * NPW;
    if (node0 >= N) return;

    const int g  = lane >> 3;   // edge slot within a 4-edge sub-batch
    const int qd = lane & 7;    // quad (4 dims) this lane covers

    #pragma unroll 1
    for (int ni = 0; ni < NPW; ++ni) {
        const int node = node0 + ni;
        if (node >= N) break;
        const int beg = g_row_ptr[node];
        const int end = g_row_ptr[node + 1];

        float4 q4 = *reinterpret_cast<const float4*>(X + (size_t)node * DK + qd * 4);
        q4.x *= (1.f / DK); q4.y *= (1.f / DK); q4.z *= (1.f / DK); q4.w *= (1.f / DK);

        float4 acc = make_float4(0.f, 0.f, 0.f, 0.f);
        float lsum = 0.f;

        int base = beg;
        // Full (unmasked) iterations: unroll 2 -> up to 16 edges / 4 KV lines
        // in flight per warp.
        #pragma unroll 2
        for (; base + 8 <= end; base += 8) {
            const unsigned oA = (unsigned)__ldg(&src[base + g])     * 8u + qd;
            const unsigned oB = (unsigned)__ldg(&src[base + 4 + g]) * 8u + qd;
            const uint4 ha = reinterpret_cast<const uint4*>(g_KV)[oA];
            const uint4 hb = reinterpret_cast<const uint4*>(g_KV)[oB];

            const float2 ka0 = __half22float2(*reinterpret_cast<const __half2*>(&ha.x));
            const float2 ka1 = __half22float2(*reinterpret_cast<const __half2*>(&ha.y));
            const float2 kb0 = __half22float2(*reinterpret_cast<const __half2*>(&hb.x));
            const float2 kb1 = __half22float2(*reinterpret_cast<const __half2*>(&hb.y));

            float dA = q4.x*ka0.x + q4.y*ka0.y + q4.z*ka1.x + q4.w*ka1.y;
            float dB = q4.x*kb0.x + q4.y*kb0.y + q4.z*kb1.x + q4.w*kb1.y;
            #pragma unroll
            for (int o = 1; o <= 4; o <<= 1) {
                dA += __shfl_xor_sync(FULL, dA, o);
                dB += __shfl_xor_sync(FULL, dB, o);
            }
            const float pA = __expf(dA);
            const float pB = __expf(dB);
            lsum += pA + pB;

            const float2 va0 = __half22float2(*reinterpret_cast<const __half2*>(&ha.z));
            const float2 va1 = __half22float2(*reinterpret_cast<const __half2*>(&ha.w));
            const float2 vb0 = __half22float2(*reinterpret_cast<const __half2*>(&hb.z));
            const float2 vb1 = __half22float2(*reinterpret_cast<const __half2*>(&hb.w));
            acc.x += pA * va0.x + pB * vb0.x;
            acc.y += pA * va0.y + pB * vb0.y;
            acc.z += pA * va1.x + pB * vb1.x;
            acc.w += pA * va1.y + pB * vb1.y;
        }

        // One masked tail iteration.
        if (base < end) {
            const int eA = base + g;
            const int eB = base + 4 + g;
            const bool mA = (eA < end);
            const bool mB = (eB < end);
            const unsigned oA = (unsigned)__ldg(&src[mA ? eA : beg]) * 8u + qd;
            const unsigned oB = (unsigned)__ldg(&src[mB ? eB : beg]) * 8u + qd;
            const uint4 ha = reinterpret_cast<const uint4*>(g_KV)[oA];
            const uint4 hb = reinterpret_cast<const uint4*>(g_KV)[oB];

            const float2 ka0 = __half22float2(*reinterpret_cast<const __half2*>(&ha.x));
            const float2 ka1 = __half22float2(*reinterpret_cast<const __half2*>(&ha.y));
            const float2 kb0 = __half22float2(*reinterpret_cast<const __half2*>(&hb.x));
            const float2 kb1 = __half22float2(*reinterpret_cast<const __half2*>(&hb.y));

            float dA = q4.x*ka0.x + q4.y*ka0.y + q4.z*ka1.x + q4.w*ka1.y;
            float dB = q4.x*kb0.x + q4.y*kb0.y + q4.z*kb1.x + q4.w*kb1.y;
            #pragma unroll
            for (int o = 1; o <= 4; o <<= 1) {
                dA += __shfl_xor_sync(FULL, dA, o);
                dB += __shfl_xor_sync(FULL, dB, o);
            }
            const float pA = mA ? __expf(dA) : 0.f;
            const float pB = mB ? __expf(dB) : 0.f;
            lsum += pA + pB;

            const float2 va0 = __half22float2(*reinterpret_cast<const __half2*>(&ha.z));
            const float2 va1 = __half22float2(*reinterpret_cast<const __half2*>(&ha.w));
            const float2 vb0 = __half22float2(*reinterpret_cast<const __half2*>(&hb.z));
            const float2 vb1 = __half22float2(*reinterpret_cast<const __half2*>(&hb.w));
            acc.x += pA * va0.x + pB * vb0.x;
            acc.y += pA * va0.y + pB * vb0.y;
            acc.z += pA * va1.x + pB * vb1.x;
            acc.w += pA * va1.y + pB * vb1.y;
        }

        // Reduce acc + lsum across the 4 edge-groups (bits 3,4 only).
        #pragma unroll
        for (int o = 8; o <= 16; o <<= 1) {
            acc.x += __shfl_xor_sync(FULL, acc.x, o);
            acc.y += __shfl_xor_sync(FULL, acc.y, o);
            acc.z += __shfl_xor_sync(FULL, acc.z, o);
            acc.w += __shfl_xor_sync(FULL, acc.w, o);
            lsum  += __shfl_xor_sync(FULL, lsum,  o);
        }
        const float inv = (lsum > 0.f) ? (1.f / lsum) : 0.f;

        // Transpose agg into smem: lanes 0..7 hold quads 0..7.
        __syncwarp();
        if (lane < 8)
            *reinterpret_cast<float4*>(&sAgg[wib][lane * 4]) = acc;
        __syncwarp();

        // Projection via transposed Wo: 8x (broadcast LDS.128 + lane LDS.128 + 4 FMA).
        float o = 0.f;
        #pragma unroll
        for (int dq = 0; dq < 8; ++dq) {
            const float4 a  = *reinterpret_cast<const float4*>(&sAgg[wib][dq * 4]);
            const float4 wt = sWoT4[lane][dq];
            o += a.x * wt.x + a.y * wt.y + a.z * wt.z + a.w * wt.w;
        }
        __stcs(&out[(size_t)node * ODIM + lane], o * inv + sBo[lane]);
    }
}

extern "C" void kernel_launch(void* const* d_in, const int* in_sizes, int n_in,
                              void* d_out, int out_size) {
    const float* X   = (const float*)d_in[0];
    const float* K   = (const float*)d_in[1];
    const float* V   = (const float*)d_in[2];
    const float* Wo  = (const float*)d_in[3];
    const float* bo  = (const float*)d_in[4];
    const int*   src = (const int*)d_in[5];
    const int*   dst = (const int*)d_in[6];

    const int N = in_sizes[0] / DK;   // 100000
    const int E = in_sizes[5];        // 1600000

    const int packBlocks = (N * 8 + 255) / 256;          // 3125
    const int rpBlocks   = ((E + 3) / 4 + 255) / 256;    // 1563
    prep_kernel<<<packBlocks + rpBlocks, 256>>>(K, V, dst, N, E, packBlocks);

    const int warps  = (N + NPW - 1) / NPW;              // 50000
    const int blocks = (warps + WPB - 1) / WPB;          // 12500
    gat_kernel<<<blocks, 32 * WPB>>>(X, Wo, bo, src, (float*)d_out, N);
}

// round 11
// speedup vs baseline: 1.1166x; 1.1166x over previous
#include <cuda_runtime.h>
#include <cuda_fp16.h>

#define DK 32
#define ODIM 32
#define MAX_NODES 100002
#define MAX_N 100000
#define NPW 2            // nodes per warp
#define WPB 4            // warps per block (block = 128 threads)

// Scratch (device globals — no allocation in kernel_launch)
__device__ int g_row_ptr[MAX_NODES];
// Packed per-node 128B line of 16B chunks; chunk qd = [K quad qd | V' quad qd]
// halves, where V' = V @ Wo (projection folded into V).
__device__ __align__(16) __half g_KV[MAX_N * 2 * DK];

// ---------------------------------------------------------------------------
// Prep kernel (fused, 3 block ranges):
//   [0, kpackBlocks)             : pack K quads to fp16 (8B writes)
//   [kpackBlocks, +vprojBlocks)  : V' = V @ Wo, packed fp16 into V-half
//   remainder                    : CSR row pointers (4 edges/thread, int4)
// ---------------------------------------------------------------------------
__global__ __launch_bounds__(256) void prep_kernel(
    const float* __restrict__ Kf,
    const float* __restrict__ Vf,
    const float* __restrict__ Wo,
    const int*   __restrict__ dst,
    int N, int E, int kpackBlocks, int vprojBlocks)
{
    __shared__ float4 sWoT4[ODIM][9];                 // sWoT4[c][dq] = Wo[4dq..][c]
    __shared__ __align__(16) float sV[64 * DK];       // 64-node V tile

    const int b = (int)blockIdx.x;
    if (b < kpackBlocks) {
        // ---- K pack: one K quad (4 halves = 8B) per thread ----
        const int c = b * 256 + threadIdx.x;
        if (c >= N * 8) return;
        const int node = c >> 3;
        const int qd   = c & 7;
        const float4 kq = *reinterpret_cast<const float4*>(Kf + (size_t)node * DK + qd * 4);
        __half2 h0 = __floats2half2_rn(kq.x, kq.y);
        __half2 h1 = __floats2half2_rn(kq.z, kq.w);
        uint2 o;
        o.x = *reinterpret_cast<unsigned*>(&h0);
        o.y = *reinterpret_cast<unsigned*>(&h1);
        // chunk qd occupies halves [qd*8 .. qd*8+7]; K quad = first 4 halves
        reinterpret_cast<uint2*>(g_KV)[(size_t)node * 16 + qd * 2] = o;
    } else if (b < kpackBlocks + vprojBlocks) {
        // ---- V' = V @ Wo for a 64-node tile; write fp16 into V-half ----
        for (int i = threadIdx.x; i < DK * ODIM; i += 256) {
            const int d = i >> 5, c = i & 31;
            reinterpret_cast<float*>(&sWoT4[c][0])[d] = Wo[i];
        }
        const int tile = (b - kpackBlocks) * 64;
        for (int i = threadIdx.x; i < 64 * DK / 4; i += 256) {
            const int gidx = tile * (DK / 4) + i;
            float4 v = make_float4(0.f, 0.f, 0.f, 0.f);
            if (gidx < N * (DK / 4))
                v = reinterpret_cast<const float4*>(Vf)[gidx];
            reinterpret_cast<float4*>(sV)[i] = v;
        }
        __syncthreads();

        const int lane = threadIdx.x & 31;     // output column c
        const int w    = threadIdx.x >> 5;     // warp -> local nodes 8w..8w+7

        float o[8];
        #pragma unroll
        for (int n = 0; n < 8; ++n) o[n] = 0.f;
        #pragma unroll
        for (int dq = 0; dq < 8; ++dq) {
            const float4 wt = sWoT4[lane][dq];
            #pragma unroll
            for (int n = 0; n < 8; ++n) {
                const float4 a = *reinterpret_cast<const float4*>(&sV[(w * 8 + n) * DK + dq * 4]);
                o[n] += a.x * wt.x + a.y * wt.y + a.z * wt.z + a.w * wt.w;
            }
        }
        #pragma unroll
        for (int n = 0; n < 8; ++n) {
            const int node = tile + w * 8 + n;
            if (node < N) {
                // V' col c lives at half-index node*64 + (c>>2)*8 + 4 + (c&3)
                g_KV[(size_t)node * 64 + (lane >> 2) * 8 + 4 + (lane & 3)] =
                    __float2half_rn(o[n]);
            }
        }
    } else {
        // ---- Row pointers: 4 edges per thread ----
        const int t  = (b - kpackBlocks - vprojBlocks) * 256 + threadIdx.x;
        const int e0 = t * 4;
        if (e0 >= E) return;
        int ds[4];
        if (e0 + 3 < E) {
            const int4 d4 = *reinterpret_cast<const int4*>(dst + e0);
            ds[0] = d4.x; ds[1] = d4.y; ds[2] = d4.z; ds[3] = d4.w;
        } else {
            #pragma unroll
            for (int j = 0; j < 4; ++j) ds[j] = (e0 + j < E) ? dst[e0 + j] : 0;
        }
        int p = (e0 > 0) ? dst[e0 - 1] : -1;
        #pragma unroll
        for (int j = 0; j < 4; ++j) {
            const int e = e0 + j;
            if (e < E) {
                const int d = ds[j];
                for (int n = p + 1; n <= d; ++n) g_row_ptr[n] = e;
                p = d;
                if (e == E - 1)
                    for (int n = d + 1; n <= N; ++n) g_row_ptr[n] = E;
            }
        }
    }
}

// ---------------------------------------------------------------------------
// Fused gat kernel: one warp per NPW nodes; 8-lane groups fetch ONE packed
// [K|V'] line per edge. Epilogue = group reduce + rcp + one 128B store.
// No shared memory, no block sync.
// ---------------------------------------------------------------------------
__global__ __launch_bounds__(128, 11) void gat_kernel(
    const float* __restrict__ X,
    const float* __restrict__ bo,
    const int*   __restrict__ src,
    float* __restrict__ out,
    int N)
{
    const unsigned FULL = 0xffffffffu;
    const int lane = threadIdx.x & 31;
    const int warp = (blockIdx.x * blockDim.x + threadIdx.x) >> 5;
    const int node0 = warp * NPW;
    if (node0 >= N) return;

    const int g  = lane >> 3;   // edge slot within a 4-edge sub-batch
    const int qd = lane & 7;    // quad (4 dims) this lane covers

    // Bias quad for the store lanes (b is tiny; one broadcast-friendly load).
    float4 bq = make_float4(0.f, 0.f, 0.f, 0.f);
    if (lane < 8) bq = reinterpret_cast<const float4*>(bo)[lane];

    #pragma unroll 1
    for (int ni = 0; ni < NPW; ++ni) {
        const int node = node0 + ni;
        if (node >= N) break;
        const int beg = g_row_ptr[node];
        const int end = g_row_ptr[node + 1];

        float4 q4 = *reinterpret_cast<const float4*>(X + (size_t)node * DK + qd * 4);
        q4.x *= (1.f / DK); q4.y *= (1.f / DK); q4.z *= (1.f / DK); q4.w *= (1.f / DK);

        float4 acc = make_float4(0.f, 0.f, 0.f, 0.f);
        float lsum = 0.f;

        int base = beg;
        // Full (unmasked) iterations: 8 edges = 2 sub-batches of 4.
        for (; base + 8 <= end; base += 8) {
            const unsigned oA = (unsigned)__ldg(&src[base + g])     * 8u + qd;
            const unsigned oB = (unsigned)__ldg(&src[base + 4 + g]) * 8u + qd;
            const uint4 ha = reinterpret_cast<const uint4*>(g_KV)[oA];
            const uint4 hb = reinterpret_cast<const uint4*>(g_KV)[oB];

            const float2 ka0 = __half22float2(*reinterpret_cast<const __half2*>(&ha.x));
            const float2 ka1 = __half22float2(*reinterpret_cast<const __half2*>(&ha.y));
            const float2 kb0 = __half22float2(*reinterpret_cast<const __half2*>(&hb.x));
            const float2 kb1 = __half22float2(*reinterpret_cast<const __half2*>(&hb.y));

            float dA = q4.x*ka0.x + q4.y*ka0.y + q4.z*ka1.x + q4.w*ka1.y;
            float dB = q4.x*kb0.x + q4.y*kb0.y + q4.z*kb1.x + q4.w*kb1.y;
            #pragma unroll
            for (int o = 1; o <= 4; o <<= 1) {
                dA += __shfl_xor_sync(FULL, dA, o);
                dB += __shfl_xor_sync(FULL, dB, o);
            }
            const float pA = __expf(dA);
            const float pB = __expf(dB);
            lsum += pA + pB;

            const float2 va0 = __half22float2(*reinterpret_cast<const __half2*>(&ha.z));
            const float2 va1 = __half22float2(*reinterpret_cast<const __half2*>(&ha.w));
            const float2 vb0 = __half22float2(*reinterpret_cast<const __half2*>(&hb.z));
            const float2 vb1 = __half22float2(*reinterpret_cast<const __half2*>(&hb.w));
            acc.x += pA * va0.x + pB * vb0.x;
            acc.y += pA * va0.y + pB * vb0.y;
            acc.z += pA * va1.x + pB * vb1.x;
            acc.w += pA * va1.y + pB * vb1.y;
        }

        // One masked tail iteration.
        if (base < end) {
            const int eA = base + g;
            const int eB = base + 4 + g;
            const bool mA = (eA < end);
            const bool mB = (eB < end);
            const unsigned oA = (unsigned)__ldg(&src[mA ? eA : beg]) * 8u + qd;
            const unsigned oB = (unsigned)__ldg(&src[mB ? eB : beg]) * 8u + qd;
            const uint4 ha = reinterpret_cast<const uint4*>(g_KV)[oA];
            const uint4 hb = reinterpret_cast<const uint4*>(g_KV)[oB];

            const float2 ka0 = __half22float2(*reinterpret_cast<const __half2*>(&ha.x));
            const float2 ka1 = __half22float2(*reinterpret_cast<const __half2*>(&ha.y));
            const float2 kb0 = __half22float2(*reinterpret_cast<const __half2*>(&hb.x));
            const float2 kb1 = __half22float2(*reinterpret_cast<const __half2*>(&hb.y));

            float dA = q4.x*ka0.x + q4.y*ka0.y + q4.z*ka1.x + q4.w*ka1.y;
            float dB = q4.x*kb0.x + q4.y*kb0.y + q4.z*kb1.x + q4.w*kb1.y;
            #pragma unroll
            for (int o = 1; o <= 4; o <<= 1) {
                dA += __shfl_xor_sync(FULL, dA, o);
                dB += __shfl_xor_sync(FULL, dB, o);
            }
            const float pA = mA ? __expf(dA) : 0.f;
            const float pB = mB ? __expf(dB) : 0.f;
            lsum += pA + pB;

            const float2 va0 = __half22float2(*reinterpret_cast<const __half2*>(&ha.z));
            const float2 va1 = __half22float2(*reinterpret_cast<const __half2*>(&ha.w));
            const float2 vb0 = __half22float2(*reinterpret_cast<const __half2*>(&hb.z));
            const float2 vb1 = __half22float2(*reinterpret_cast<const __half2*>(&hb.w));
            acc.x += pA * va0.x + pB * vb0.x;
            acc.y += pA * va0.y + pB * vb0.y;
            acc.z += pA * va1.x + pB * vb1.x;
            acc.w += pA * va1.y + pB * vb1.y;
        }

        // Reduce acc + lsum across the 4 edge-groups (bits 3,4 only).
        #pragma unroll
        for (int o = 8; o <= 16; o <<= 1) {
            acc.x += __shfl_xor_sync(FULL, acc.x, o);
            acc.y += __shfl_xor_sync(FULL, acc.y, o);
            acc.z += __shfl_xor_sync(FULL, acc.z, o);
            acc.w += __shfl_xor_sync(FULL, acc.w, o);
            lsum  += __shfl_xor_sync(FULL, lsum,  o);
        }
        const float inv = (lsum > 0.f) ? (1.f / lsum) : 0.f;

        // Projection already folded into V': lanes 0..7 hold output quads 0..7.
        if (lane < 8) {
            float4 r;
            r.x = acc.x * inv + bq.x;
            r.y = acc.y * inv + bq.y;
            r.z = acc.z * inv + bq.z;
            r.w = acc.w * inv + bq.w;
            *reinterpret_cast<float4*>(&out[(size_t)node * ODIM + lane * 4]) = r;
        }
    }
}

extern "C" void kernel_launch(void* const* d_in, const int* in_sizes, int n_in,
                              void* d_out, int out_size) {
    const float* X   = (const float*)d_in[0];
    const float* K   = (const float*)d_in[1];
    const float* V   = (const float*)d_in[2];
    const float* Wo  = (const float*)d_in[3];
    const float* bo  = (const float*)d_in[4];
    const int*   src = (const int*)d_in[5];
    const int*   dst = (const int*)d_in[6];

    const int N = in_sizes[0] / DK;   // 100000
    const int E = in_sizes[5];        // 1600000

    const int kpackBlocks = (N * 8 + 255) / 256;         // 3125
    const int vprojBlocks = (N + 63) / 64;               // 1563
    const int rpBlocks    = ((E + 3) / 4 + 255) / 256;   // 1563
    prep_kernel<<<kpackBlocks + vprojBlocks + rpBlocks, 256>>>(
        K, V, Wo, dst, N, E, kpackBlocks, vprojBlocks);

    const int warps  = (N + NPW - 1) / NPW;              // 50000
    const int blocks = (warps + WPB - 1) / WPB;          // 12500
    gat_kernel<<<blocks, 32 * WPB>>>(X, bo, src, (float*)d_out, N);
}